// round 1
// baseline (speedup 1.0000x reference)
#include <cuda_runtime.h>
#include <cuda_bf16.h>

#define NN    204800   // nodes
#define HH    256      // hidden
#define EE    819200   // edges
#define BB    8192     // graphs
#define NROOTC 2048
#define FPD   4096
#define NFD   128
#define NPGC  25
#define LLC   2

// ---------------- scratch (device globals; no allocation allowed) ----------
__device__ float g_frag_h[NN * HH];        // 210 MB
__device__ float g_m[NN * HH];             // msg buf / h1
__device__ float g_a[NN * HH];             // aggregated / h2
__device__ float g_gi[NN * 3 * HH];        // 629 MB
__device__ float g_gh[NN * 3 * HH];        // 629 MB
__device__ float g_root_emb[NROOTC * HH];
__device__ float g_ext_root[BB * HH];
__device__ float g_avg[BB * HH];
__device__ float g_gpre[BB * HH];
__device__ float g_Wab[HH * HH];

// ---------------- generic tiled SGEMM: C = A[M,K] @ W[K,Nc] (+epilogue) ----
// MODE 0: +bias
// MODE 1: relu(+bias)
// MODE 2: relu(acc + rowvec[row/25][col])      (h1 = frag@W1c + g_pre)
// MODE 3: acc + bias + w1d[broken[row]][col]   (per-graph pre-vector, part 1)
// MODE 4: C = C_old - acc                      (per-graph pre-vector, part 2)
template <int MODE>
__global__ __launch_bounds__(256) void sgemm_kernel(
    const float* __restrict__ A, const float* __restrict__ W,
    const float* __restrict__ bias, float* __restrict__ C,
    int M, int K, int Nc,
    const float* __restrict__ rowvec,
    const int* __restrict__ broken,
    const float* __restrict__ w1d)
{
    __shared__ float As[16][64];
    __shared__ float Bs[16][64];

    const int tid = threadIdx.x;
    const int rowBase = blockIdx.y * 64;
    const int colBase = blockIdx.x * 64;

    const int arow = tid >> 2;          // 0..63
    const int ak   = (tid & 3) * 4;     // 0,4,8,12
    const int bk   = tid >> 4;          // 0..15
    const int bn   = (tid & 15) * 4;    // 0..60

    const int ty = tid >> 4;            // 0..15
    const int tx = tid & 15;            // 0..15

    float acc[4][4] = {};

    const float* Aptr = A + (size_t)(rowBase + arow) * K + ak;
    const float* Wptr = W + (size_t)bk * Nc + colBase + bn;

    for (int kt = 0; kt < K; kt += 16) {
        float4 av = *(const float4*)(Aptr + kt);
        As[ak + 0][arow] = av.x;
        As[ak + 1][arow] = av.y;
        As[ak + 2][arow] = av.z;
        As[ak + 3][arow] = av.w;
        float4 bv = *(const float4*)(Wptr + (size_t)kt * Nc);
        *(float4*)&Bs[bk][bn] = bv;
        __syncthreads();

#pragma unroll
        for (int k = 0; k < 16; k++) {
            float4 a4 = *(const float4*)&As[k][ty * 4];
            float4 b4 = *(const float4*)&Bs[k][tx * 4];
            float ar[4] = {a4.x, a4.y, a4.z, a4.w};
            float br[4] = {b4.x, b4.y, b4.z, b4.w};
#pragma unroll
            for (int i = 0; i < 4; i++)
#pragma unroll
                for (int j = 0; j < 4; j++)
                    acc[i][j] = fmaf(ar[i], br[j], acc[i][j]);
        }
        __syncthreads();
    }

#pragma unroll
    for (int i = 0; i < 4; i++) {
        const int row = rowBase + ty * 4 + i;
#pragma unroll
        for (int j = 0; j < 4; j++) {
            const int col = colBase + tx * 4 + j;
            float v = acc[i][j];
            if (MODE == 0) {
                v += bias[col];
            } else if (MODE == 1) {
                v += bias[col];
                v = fmaxf(v, 0.0f);
            } else if (MODE == 2) {
                v += rowvec[(row / NPGC) * Nc + col];
                v = fmaxf(v, 0.0f);
            } else if (MODE == 3) {
                v += bias[col] + w1d[broken[row] * Nc + col];
            } else if (MODE == 4) {
                v = C[(size_t)row * Nc + col] - v;
            }
            C[(size_t)row * Nc + col] = v;
        }
    }
}

// ---------------- edge scatter-add: a[dst] += m[src] -----------------------
__global__ void scatter_kernel(const float* __restrict__ m,
                               const int* __restrict__ src,
                               const int* __restrict__ dst,
                               float* __restrict__ a)
{
    const int e = blockIdx.x;
    const int c = threadIdx.x;
    const int s = __ldg(&src[e]);
    const int d = __ldg(&dst[e]);
    atomicAdd(&a[(size_t)d * HH + c], m[(size_t)s * HH + c]);
}

__global__ void zero_kernel(float4* __restrict__ p, int n4)
{
    int i = blockIdx.x * blockDim.x + threadIdx.x;
    if (i < n4) p[i] = make_float4(0.f, 0.f, 0.f, 0.f);
}

// ---------------- fused GRU gate update -----------------------------------
__global__ void gru_kernel(const float* __restrict__ gi,
                           const float* __restrict__ gh,
                           float* __restrict__ h)
{
    const int idx = blockIdx.x * blockDim.x + threadIdx.x; // over NN*HH
    const int n = idx >> 8;
    const int c = idx & 255;
    const size_t base = (size_t)n * (3 * HH);
    const float ir = gi[base + c];
    const float iz = gi[base + HH + c];
    const float inn = gi[base + 2 * HH + c];
    const float hr = gh[base + c];
    const float hz = gh[base + HH + c];
    const float hn = gh[base + 2 * HH + c];
    const float r = 1.0f / (1.0f + expf(-(ir + hr)));
    const float z = 1.0f / (1.0f + expf(-(iz + hz)));
    const float nv = tanhf(inn + r * hn);
    const float hv = h[idx];
    h[idx] = (1.0f - z) * nv + z * hv;
}

// ---------------- segment mean over contiguous 25-row graphs ---------------
__global__ void pool_kernel(const float* __restrict__ h, float* __restrict__ avg)
{
    const int g = blockIdx.x;
    const int c = threadIdx.x;
    const float* base = h + (size_t)g * NPGC * HH + c;
    float s = 0.0f;
#pragma unroll
    for (int i = 0; i < NPGC; i++) s += base[(size_t)i * HH];
    avg[(size_t)g * HH + c] = s * (1.0f / NPGC);
}

__global__ void gather_root_kernel(const float* __restrict__ emb,
                                   const int* __restrict__ ind,
                                   float* __restrict__ out)
{
    const int g = blockIdx.x;
    const int c = threadIdx.x;
    out[(size_t)g * HH + c] = emb[(size_t)__ldg(&ind[g]) * HH + c];
}

// Wab = W1a + W1b (rows 0..255 plus rows 256..511 of mlp_W1)
__global__ void wab_kernel(const float* __restrict__ W1, float* __restrict__ wab)
{
    const int i = blockIdx.x * blockDim.x + threadIdx.x; // HH*HH
    wab[i] = W1[i] + W1[HH * HH + i];
}

// out[n] = sigmoid(dot(h2[n], out_W) + out_b)
__global__ void outdot_kernel(const float* __restrict__ h2,
                              const float* __restrict__ outW,
                              const float* __restrict__ outb,
                              float* __restrict__ out)
{
    const int row = blockIdx.x * 8 + (threadIdx.x >> 5);
    const int lane = threadIdx.x & 31;
    const float* p = h2 + (size_t)row * HH;
    float s = 0.0f;
#pragma unroll
    for (int i = 0; i < 8; i++) s += p[lane + i * 32] * outW[lane + i * 32];
#pragma unroll
    for (int off = 16; off; off >>= 1) s += __shfl_xor_sync(0xffffffff, s, off);
    if (lane == 0) out[row] = 1.0f / (1.0f + expf(-(s + outb[0])));
}

// ---------------------------------------------------------------------------
extern "C" void kernel_launch(void* const* d_in, const int* in_sizes, int n_in,
                              void* d_out, int out_size)
{
    const float* node_x    = (const float*)d_in[0];
    const float* root_fp   = (const float*)d_in[1];
    const int*   edge_src  = (const int*)d_in[2];
    const int*   edge_dst  = (const int*)d_in[3];
    const int*   ind_maps  = (const int*)d_in[4];
    const int*   broken    = (const int*)d_in[5];
    /* d_in[6] node2graph unused: graph = row/25 */
    const float* root_W    = (const float*)d_in[7];
    const float* root_b    = (const float*)d_in[8];
    const float* node_in_W = (const float*)d_in[9];
    const float* node_in_b = (const float*)d_in[10];
    const float* edge_W    = (const float*)d_in[11];
    const float* edge_b    = (const float*)d_in[12];
    const float* W_ih      = (const float*)d_in[13];
    const float* b_ih      = (const float*)d_in[14];
    const float* W_hh      = (const float*)d_in[15];
    const float* b_hh      = (const float*)d_in[16];
    const float* mlp_W1    = (const float*)d_in[17];
    const float* mlp_b1    = (const float*)d_in[18];
    const float* mlp_W2    = (const float*)d_in[19];
    const float* mlp_b2    = (const float*)d_in[20];
    const float* out_W     = (const float*)d_in[21];
    const float* out_b     = (const float*)d_in[22];
    float* out = (float*)d_out;

    float *frag_h, *mbuf, *abuf, *gi, *gh, *root_emb, *ext_root, *avg, *gpre, *wab;
    cudaGetSymbolAddress((void**)&frag_h,   g_frag_h);
    cudaGetSymbolAddress((void**)&mbuf,     g_m);
    cudaGetSymbolAddress((void**)&abuf,     g_a);
    cudaGetSymbolAddress((void**)&gi,       g_gi);
    cudaGetSymbolAddress((void**)&gh,       g_gh);
    cudaGetSymbolAddress((void**)&root_emb, g_root_emb);
    cudaGetSymbolAddress((void**)&ext_root, g_ext_root);
    cudaGetSymbolAddress((void**)&avg,      g_avg);
    cudaGetSymbolAddress((void**)&gpre,     g_gpre);
    cudaGetSymbolAddress((void**)&wab,      g_Wab);

    // root encoder: relu(root_fp @ root_W + root_b)
    sgemm_kernel<1><<<dim3(HH / 64, NROOTC / 64), 256>>>(
        root_fp, root_W, root_b, root_emb, NROOTC, FPD, HH, nullptr, nullptr, nullptr);

    // node input: frag_h = node_x @ node_in_W + b
    sgemm_kernel<0><<<dim3(HH / 64, NN / 64), 256>>>(
        node_x, node_in_W, node_in_b, frag_h, NN, NFD, HH, nullptr, nullptr, nullptr);

    for (int l = 0; l < LLC; l++) {
        // m = frag_h @ edge_W[l] + edge_b[l]
        sgemm_kernel<0><<<dim3(HH / 64, NN / 64), 256>>>(
            frag_h, edge_W + (size_t)l * HH * HH, edge_b + (size_t)l * HH,
            mbuf, NN, HH, HH, nullptr, nullptr, nullptr);

        // a = scatter_add(m[src] -> dst)
        zero_kernel<<<(NN * HH / 4 + 255) / 256, 256>>>((float4*)abuf, NN * HH / 4);
        scatter_kernel<<<EE, HH>>>(mbuf, edge_src, edge_dst, abuf);

        // gi = a @ W_ih[l] + b_ih[l] ; gh = frag_h @ W_hh[l] + b_hh[l]
        sgemm_kernel<0><<<dim3(3 * HH / 64, NN / 64), 256>>>(
            abuf, W_ih + (size_t)l * HH * 3 * HH, b_ih + (size_t)l * 3 * HH,
            gi, NN, HH, 3 * HH, nullptr, nullptr, nullptr);
        sgemm_kernel<0><<<dim3(3 * HH / 64, NN / 64), 256>>>(
            frag_h, W_hh + (size_t)l * HH * 3 * HH, b_hh + (size_t)l * 3 * HH,
            gh, NN, HH, 3 * HH, nullptr, nullptr, nullptr);

        gru_kernel<<<NN * HH / 256, 256>>>(gi, gh, frag_h);
    }

    // per-graph pooling + precomputed per-graph MLP vector
    pool_kernel<<<BB, HH>>>(frag_h, avg);
    gather_root_kernel<<<BB, HH>>>(root_emb, ind_maps, ext_root);
    wab_kernel<<<HH * HH / 256, 256>>>(mlp_W1, wab);

    // g_pre = ext_root @ (W1a+W1b) + b1 + W1d[broken]
    sgemm_kernel<3><<<dim3(HH / 64, BB / 64), 256>>>(
        ext_root, wab, mlp_b1, gpre, BB, HH, HH,
        nullptr, broken, mlp_W1 + (size_t)3 * HH * HH);
    // g_pre -= avg @ W1b
    sgemm_kernel<4><<<dim3(HH / 64, BB / 64), 256>>>(
        avg, mlp_W1 + (size_t)HH * HH, nullptr, gpre, BB, HH, HH,
        nullptr, nullptr, nullptr);

    // h1 = relu(frag_h @ W1c + g_pre[row/25])   (reuse mbuf)
    sgemm_kernel<2><<<dim3(HH / 64, NN / 64), 256>>>(
        frag_h, mlp_W1 + (size_t)2 * HH * HH, nullptr, mbuf, NN, HH, HH,
        gpre, nullptr, nullptr);

    // h2 = relu(h1 @ W2 + b2)   (reuse abuf)
    sgemm_kernel<1><<<dim3(HH / 64, NN / 64), 256>>>(
        mbuf, mlp_W2, mlp_b2, abuf, NN, HH, HH, nullptr, nullptr, nullptr);

    // out = sigmoid(h2 . out_W + out_b)
    outdot_kernel<<<NN / 8, 256>>>(abuf, out_W, out_b, out);
}

// round 3
// speedup vs baseline: 2.8356x; 2.8356x over previous
#include <cuda_runtime.h>
#include <cuda_bf16.h>
#include <cstdint>

#define NN     204800   // nodes
#define HH     256      // hidden
#define EE     819200   // edges
#define BB     8192     // graphs
#define NROOTC 2048
#define FPD    4096
#define NFD    128
#define NPGC   25
#define LLC    2

// ---------------- scratch (device globals; no allocation allowed) ----------
__device__ float g_frag_h[NN * HH];
__device__ float g_m[NN * HH];
__device__ float g_a[NN * HH];
__device__ float g_gi[NN * 3 * HH];
__device__ float g_gh[NN * 3 * HH];
__device__ float g_root_emb[NROOTC * HH];
__device__ float g_ext_root[BB * HH];
__device__ float g_avg[BB * HH];
__device__ float g_gpre[BB * HH];
__device__ float g_Wab[HH * HH];

// transposed weights: Bt[n][k] = W[k][n]
#define OFF_ROOT 0
#define OFF_NIN  (OFF_ROOT + 256*4096)
#define OFF_EDGE (OFF_NIN + 256*128)
#define OFF_IH   (OFF_EDGE + 2*256*256)
#define OFF_HH2  (OFF_IH + 2*768*256)
#define OFF_W1C  (OFF_HH2 + 2*768*256)
#define OFF_W2   (OFF_W1C + 256*256)
#define WT_TOTAL (OFF_W2 + 256*256)
__device__ float g_Wt[WT_TOTAL];

// ============================ helpers ======================================
__device__ __forceinline__ uint32_t smem_u32(const void* p) {
    uint32_t a;
    asm("{ .reg .u64 t; cvta.to.shared.u64 t, %1; cvt.u32.u64 %0, t; }"
        : "=r"(a) : "l"(p));
    return a;
}
__device__ __forceinline__ uint32_t f2tf(float x) {
    uint32_t u;
    asm("cvt.rna.tf32.f32 %0, %1;" : "=r"(u) : "f"(x));
    return u;
}
__device__ __forceinline__ void mma8(float* d, const uint32_t* a, const uint32_t* b) {
    asm volatile(
        "mma.sync.aligned.m16n8k8.row.col.f32.tf32.tf32.f32 "
        "{%0,%1,%2,%3}, {%4,%5,%6,%7}, {%8,%9}, {%0,%1,%2,%3};"
        : "+f"(d[0]), "+f"(d[1]), "+f"(d[2]), "+f"(d[3])
        : "r"(a[0]), "r"(a[1]), "r"(a[2]), "r"(a[3]), "r"(b[0]), "r"(b[1]));
}
__device__ __forceinline__ void cp16(uint32_t s, const void* g) {
    asm volatile("cp.async.cg.shared.global [%0], [%1], 16;" :: "r"(s), "l"(g));
}
#define CP_COMMIT() asm volatile("cp.async.commit_group;" ::: "memory")
#define CP_WAIT(n)  asm volatile("cp.async.wait_group %0;" :: "n"(n) : "memory")

// ============ mma.sync tf32 GEMM: C[M,Nc] = A[M,K] @ Bt[Nc,K]^T ============
// CTA tile 128x128, BK=32, 256 threads, double-buffered cp.async.
// smem row stride = 36 floats (conflict-free fragment reads, 16B aligned).
// MODE 0: +bias   MODE 1: relu(+bias)   MODE 2: relu(acc + rowvec[row/25][col])
#define SSTRIDE 36
#define STAGE_F (128 * SSTRIDE * 2)      // floats per stage (A tile + B tile)
template <int MODE>
__global__ __launch_bounds__(256, 2) void mma_gemm(
    const float* __restrict__ A, const float* __restrict__ Bt,
    const float* __restrict__ bias, float* __restrict__ C,
    int M, int K, int Nc, const float* __restrict__ rowvec)
{
    extern __shared__ float sm[];
    const int tid = threadIdx.x, lane = tid & 31, wid = tid >> 5;
    const int gid = lane >> 2, tig = lane & 3;
    const int rowBase = blockIdx.y * 128, colBase = blockIdx.x * 128;
    const int wm = (wid & 1) * 64, wn = (wid >> 1) * 32;

    float acc[4][4][4] = {};

    const int c4 = tid & 7;        // float4 within 32-float row
    const int r0 = tid >> 3;       // 0..31
    const uint32_t sbase = smem_u32(sm);
    const float* Ag = A + (size_t)(rowBase + r0) * K + c4 * 4;
    const float* Bg = Bt + (size_t)(colBase + r0) * K + c4 * 4;
    const int nk = K / 32;

    // stage byte layout: [A 128*144][B 128*144]
    const uint32_t stB = 128 * SSTRIDE * 4;

    // issue chunk kc into stage st
    auto issue = [&](int kc, int st) {
        const uint32_t base = sbase + st * (STAGE_F * 4);
#pragma unroll
        for (int it = 0; it < 4; it++) {
            const int r = r0 + it * 32;
            cp16(base + r * (SSTRIDE * 4) + c4 * 16, Ag + (size_t)it * 32 * K + kc * 32);
            cp16(base + stB + r * (SSTRIDE * 4) + c4 * 16, Bg + (size_t)it * 32 * K + kc * 32);
        }
        CP_COMMIT();
    };

    issue(0, 0);
    for (int kc = 0; kc < nk; kc++) {
        if (kc + 1 < nk) { issue(kc + 1, (kc + 1) & 1); CP_WAIT(1); }
        else             { CP_WAIT(0); }
        __syncthreads();

        const float* As = sm + (kc & 1) * STAGE_F;
        const float* Bs = As + 128 * SSTRIDE;
#pragma unroll
        for (int ks = 0; ks < 4; ks++) {
            const int k0 = ks * 8 + tig;
            uint32_t af[4][4], bf[4][2];
#pragma unroll
            for (int mi = 0; mi < 4; mi++) {
                const int r = wm + mi * 16 + gid;
                af[mi][0] = f2tf(As[r * SSTRIDE + k0]);
                af[mi][1] = f2tf(As[(r + 8) * SSTRIDE + k0]);
                af[mi][2] = f2tf(As[r * SSTRIDE + k0 + 4]);
                af[mi][3] = f2tf(As[(r + 8) * SSTRIDE + k0 + 4]);
            }
#pragma unroll
            for (int ni = 0; ni < 4; ni++) {
                const int n = wn + ni * 8 + gid;
                bf[ni][0] = f2tf(Bs[n * SSTRIDE + k0]);
                bf[ni][1] = f2tf(Bs[n * SSTRIDE + k0 + 4]);
            }
#pragma unroll
            for (int mi = 0; mi < 4; mi++)
#pragma unroll
                for (int ni = 0; ni < 4; ni++)
                    mma8(acc[mi][ni], af[mi], bf[ni]);
        }
        __syncthreads();
    }

    // ---- epilogue ----
#pragma unroll
    for (int mi = 0; mi < 4; mi++) {
        const int r = rowBase + wm + mi * 16 + gid;
        const int g0 = r / NPGC, g1 = (r + 8) / NPGC;
#pragma unroll
        for (int ni = 0; ni < 4; ni++) {
            const int c = colBase + wn + ni * 8 + tig * 2;
            float v[4];
            v[0] = acc[mi][ni][0]; v[1] = acc[mi][ni][1];
            v[2] = acc[mi][ni][2]; v[3] = acc[mi][ni][3];
            if (MODE == 0) {
                v[0] += bias[c]; v[1] += bias[c + 1];
                v[2] += bias[c]; v[3] += bias[c + 1];
            } else if (MODE == 1) {
                v[0] = fmaxf(v[0] + bias[c], 0.f);
                v[1] = fmaxf(v[1] + bias[c + 1], 0.f);
                v[2] = fmaxf(v[2] + bias[c], 0.f);
                v[3] = fmaxf(v[3] + bias[c + 1], 0.f);
            } else if (MODE == 2) {
                v[0] = fmaxf(v[0] + rowvec[(size_t)g0 * HH + c], 0.f);
                v[1] = fmaxf(v[1] + rowvec[(size_t)g0 * HH + c + 1], 0.f);
                v[2] = fmaxf(v[2] + rowvec[(size_t)g1 * HH + c], 0.f);
                v[3] = fmaxf(v[3] + rowvec[(size_t)g1 * HH + c + 1], 0.f);
            }
            *(float2*)(C + (size_t)r * Nc + c)       = make_float2(v[0], v[1]);
            *(float2*)(C + (size_t)(r + 8) * Nc + c) = make_float2(v[2], v[3]);
        }
    }
}

// ---------------- 32x32 tiled transpose: out[c*R+r] = in[r*C+c] ------------
__global__ void transpose_kernel(const float* __restrict__ in,
                                 float* __restrict__ out, int R, int Ccols)
{
    __shared__ float t[32][33];
    const int c0 = blockIdx.x * 32, rr0 = blockIdx.y * 32;
    const int x = threadIdx.x, y = threadIdx.y;
    for (int i = y; i < 32; i += 8)
        t[i][x] = in[(size_t)(rr0 + i) * Ccols + c0 + x];
    __syncthreads();
    for (int i = y; i < 32; i += 8)
        out[(size_t)(c0 + i) * R + rr0 + x] = t[x][i];
}

// -------------- fp32 SGEMM for the tiny per-graph GEMMs --------------------
// MODE 3: acc + bias + w1d[broken[row]][col]
// MODE 4: C = C_old - acc
template <int MODE>
__global__ __launch_bounds__(256) void sgemm_kernel(
    const float* __restrict__ A, const float* __restrict__ W,
    const float* __restrict__ bias, float* __restrict__ C,
    int M, int K, int Nc,
    const int* __restrict__ broken, const float* __restrict__ w1d)
{
    __shared__ float As[16][64];
    __shared__ float Bs[16][64];
    const int tid = threadIdx.x;
    const int rowBase = blockIdx.y * 64, colBase = blockIdx.x * 64;
    const int arow = tid >> 2, ak = (tid & 3) * 4;
    const int bk = tid >> 4, bn = (tid & 15) * 4;
    const int ty = tid >> 4, tx = tid & 15;
    float acc[4][4] = {};
    const float* Aptr = A + (size_t)(rowBase + arow) * K + ak;
    const float* Wptr = W + (size_t)bk * Nc + colBase + bn;
    for (int kt = 0; kt < K; kt += 16) {
        float4 av = *(const float4*)(Aptr + kt);
        As[ak][arow] = av.x; As[ak + 1][arow] = av.y;
        As[ak + 2][arow] = av.z; As[ak + 3][arow] = av.w;
        *(float4*)&Bs[bk][bn] = *(const float4*)(Wptr + (size_t)kt * Nc);
        __syncthreads();
#pragma unroll
        for (int k = 0; k < 16; k++) {
            float4 a4 = *(const float4*)&As[k][ty * 4];
            float4 b4 = *(const float4*)&Bs[k][tx * 4];
            float ar[4] = {a4.x, a4.y, a4.z, a4.w};
            float br[4] = {b4.x, b4.y, b4.z, b4.w};
#pragma unroll
            for (int i = 0; i < 4; i++)
#pragma unroll
                for (int j = 0; j < 4; j++)
                    acc[i][j] = fmaf(ar[i], br[j], acc[i][j]);
        }
        __syncthreads();
    }
#pragma unroll
    for (int i = 0; i < 4; i++) {
        const int row = rowBase + ty * 4 + i;
#pragma unroll
        for (int j = 0; j < 4; j++) {
            const int col = colBase + tx * 4 + j;
            float v = acc[i][j];
            if (MODE == 3) v += bias[col] + w1d[broken[row] * Nc + col];
            else if (MODE == 4) v = C[(size_t)row * Nc + col] - v;
            C[(size_t)row * Nc + col] = v;
        }
    }
}

// ---------------- edge scatter-add ----------------------------------------
__global__ void scatter_kernel(const float* __restrict__ m,
                               const int* __restrict__ src,
                               const int* __restrict__ dst,
                               float* __restrict__ a)
{
    const int e = blockIdx.x * 4 + (threadIdx.x >> 6);
    const int c = (threadIdx.x & 63) * 4;
    const int s = __ldg(&src[e]);
    const int d = __ldg(&dst[e]);
    float4 v = *(const float4*)(m + (size_t)s * HH + c);
    float* out = a + (size_t)d * HH + c;
    atomicAdd(out + 0, v.x); atomicAdd(out + 1, v.y);
    atomicAdd(out + 2, v.z); atomicAdd(out + 3, v.w);
}

__global__ void zero_kernel(float4* __restrict__ p, int n4)
{
    int i = blockIdx.x * blockDim.x + threadIdx.x;
    if (i < n4) p[i] = make_float4(0.f, 0.f, 0.f, 0.f);
}

// ---------------- fused GRU gate update -----------------------------------
__global__ void gru_kernel(const float* __restrict__ gi,
                           const float* __restrict__ gh,
                           float* __restrict__ h)
{
    const int idx = blockIdx.x * blockDim.x + threadIdx.x;
    const int n = idx >> 8;
    const int c = idx & 255;
    const size_t base = (size_t)n * (3 * HH);
    const float ir = gi[base + c];
    const float iz = gi[base + HH + c];
    const float inn = gi[base + 2 * HH + c];
    const float hr = gh[base + c];
    const float hz = gh[base + HH + c];
    const float hn = gh[base + 2 * HH + c];
    const float r = 1.0f / (1.0f + expf(-(ir + hr)));
    const float z = 1.0f / (1.0f + expf(-(iz + hz)));
    const float nv = tanhf(inn + r * hn);
    const float hv = h[idx];
    h[idx] = (1.0f - z) * nv + z * hv;
}

// ---------------- pooling / gathers / head --------------------------------
__global__ void pool_kernel(const float* __restrict__ h, float* __restrict__ avg)
{
    const int g = blockIdx.x, c = threadIdx.x;
    const float* base = h + (size_t)g * NPGC * HH + c;
    float s = 0.0f;
#pragma unroll
    for (int i = 0; i < NPGC; i++) s += base[(size_t)i * HH];
    avg[(size_t)g * HH + c] = s * (1.0f / NPGC);
}

__global__ void gather_root_kernel(const float* __restrict__ emb,
                                   const int* __restrict__ ind,
                                   float* __restrict__ out)
{
    const int g = blockIdx.x, c = threadIdx.x;
    out[(size_t)g * HH + c] = emb[(size_t)__ldg(&ind[g]) * HH + c];
}

__global__ void wab_kernel(const float* __restrict__ W1, float* __restrict__ wab)
{
    const int i = blockIdx.x * blockDim.x + threadIdx.x;
    wab[i] = W1[i] + W1[HH * HH + i];
}

__global__ void outdot_kernel(const float* __restrict__ h2,
                              const float* __restrict__ outW,
                              const float* __restrict__ outb,
                              float* __restrict__ out)
{
    const int row = blockIdx.x * 8 + (threadIdx.x >> 5);
    const int lane = threadIdx.x & 31;
    const float* p = h2 + (size_t)row * HH;
    float s = 0.0f;
#pragma unroll
    for (int i = 0; i < 8; i++) s += p[lane + i * 32] * outW[lane + i * 32];
#pragma unroll
    for (int off = 16; off; off >>= 1) s += __shfl_xor_sync(0xffffffff, s, off);
    if (lane == 0) out[row] = 1.0f / (1.0f + expf(-(s + outb[0])));
}

// ---------------------------------------------------------------------------
extern "C" void kernel_launch(void* const* d_in, const int* in_sizes, int n_in,
                              void* d_out, int out_size)
{
    const float* node_x    = (const float*)d_in[0];
    const float* root_fp   = (const float*)d_in[1];
    const int*   edge_src  = (const int*)d_in[2];
    const int*   edge_dst  = (const int*)d_in[3];
    const int*   ind_maps  = (const int*)d_in[4];
    const int*   broken    = (const int*)d_in[5];
    const float* root_W    = (const float*)d_in[7];
    const float* root_b    = (const float*)d_in[8];
    const float* node_in_W = (const float*)d_in[9];
    const float* node_in_b = (const float*)d_in[10];
    const float* edge_W    = (const float*)d_in[11];
    const float* edge_b    = (const float*)d_in[12];
    const float* W_ih      = (const float*)d_in[13];
    const float* b_ih      = (const float*)d_in[14];
    const float* W_hh      = (const float*)d_in[15];
    const float* b_hh      = (const float*)d_in[16];
    const float* mlp_W1    = (const float*)d_in[17];
    const float* mlp_b1    = (const float*)d_in[18];
    const float* mlp_W2    = (const float*)d_in[19];
    const float* mlp_b2    = (const float*)d_in[20];
    const float* out_W     = (const float*)d_in[21];
    const float* out_b     = (const float*)d_in[22];
    float* out = (float*)d_out;

    float *frag_h, *mbuf, *abuf, *gi, *gh, *root_emb, *ext_root, *avg, *gpre,
          *wab, *wt;
    cudaGetSymbolAddress((void**)&frag_h,   g_frag_h);
    cudaGetSymbolAddress((void**)&mbuf,     g_m);
    cudaGetSymbolAddress((void**)&abuf,     g_a);
    cudaGetSymbolAddress((void**)&gi,       g_gi);
    cudaGetSymbolAddress((void**)&gh,       g_gh);
    cudaGetSymbolAddress((void**)&root_emb, g_root_emb);
    cudaGetSymbolAddress((void**)&ext_root, g_ext_root);
    cudaGetSymbolAddress((void**)&avg,      g_avg);
    cudaGetSymbolAddress((void**)&gpre,     g_gpre);
    cudaGetSymbolAddress((void**)&wab,      g_Wab);
    cudaGetSymbolAddress((void**)&wt,       g_Wt);

    const int SMEM_SZ = STAGE_F * 2 * 4;   // 2 stages (A+B tiles), bytes
    cudaFuncSetAttribute(mma_gemm<0>, cudaFuncAttributeMaxDynamicSharedMemorySize, SMEM_SZ);
    cudaFuncSetAttribute(mma_gemm<1>, cudaFuncAttributeMaxDynamicSharedMemorySize, SMEM_SZ);
    cudaFuncSetAttribute(mma_gemm<2>, cudaFuncAttributeMaxDynamicSharedMemorySize, SMEM_SZ);

    // ---- transpose all weights to [Nc, K] ----
    dim3 tb(32, 8);
    transpose_kernel<<<dim3(256/32, 4096/32), tb>>>(root_W, wt + OFF_ROOT, 4096, 256);
    transpose_kernel<<<dim3(256/32, 128/32),  tb>>>(node_in_W, wt + OFF_NIN, 128, 256);
    for (int l = 0; l < LLC; l++) {
        transpose_kernel<<<dim3(8, 8),  tb>>>(edge_W + (size_t)l*HH*HH, wt + OFF_EDGE + l*HH*HH, 256, 256);
        transpose_kernel<<<dim3(24, 8), tb>>>(W_ih + (size_t)l*HH*3*HH, wt + OFF_IH + l*768*256, 256, 768);
        transpose_kernel<<<dim3(24, 8), tb>>>(W_hh + (size_t)l*HH*3*HH, wt + OFF_HH2 + l*768*256, 256, 768);
    }
    transpose_kernel<<<dim3(8, 8), tb>>>(mlp_W1 + (size_t)2*HH*HH, wt + OFF_W1C, 256, 256);
    transpose_kernel<<<dim3(8, 8), tb>>>(mlp_W2, wt + OFF_W2, 256, 256);

    // ---- root encoder: relu(root_fp @ root_W + b) ----
    mma_gemm<1><<<dim3(2, NROOTC/128), 256, SMEM_SZ>>>(
        root_fp, wt + OFF_ROOT, root_b, root_emb, NROOTC, FPD, HH, nullptr);

    // ---- node input ----
    mma_gemm<0><<<dim3(2, NN/128), 256, SMEM_SZ>>>(
        node_x, wt + OFF_NIN, node_in_b, frag_h, NN, NFD, HH, nullptr);

    for (int l = 0; l < LLC; l++) {
        mma_gemm<0><<<dim3(2, NN/128), 256, SMEM_SZ>>>(
            frag_h, wt + OFF_EDGE + l*HH*HH, edge_b + (size_t)l*HH,
            mbuf, NN, HH, HH, nullptr);

        zero_kernel<<<(NN * HH / 4 + 255) / 256, 256>>>((float4*)abuf, NN * HH / 4);
        scatter_kernel<<<EE / 4, 256>>>(mbuf, edge_src, edge_dst, abuf);

        mma_gemm<0><<<dim3(6, NN/128), 256, SMEM_SZ>>>(
            abuf, wt + OFF_IH + l*768*256, b_ih + (size_t)l*3*HH,
            gi, NN, HH, 3*HH, nullptr);
        mma_gemm<0><<<dim3(6, NN/128), 256, SMEM_SZ>>>(
            frag_h, wt + OFF_HH2 + l*768*256, b_hh + (size_t)l*3*HH,
            gh, NN, HH, 3*HH, nullptr);

        gru_kernel<<<NN * HH / 256, 256>>>(gi, gh, frag_h);
    }

    // ---- per-graph head pre-vector ----
    pool_kernel<<<BB, HH>>>(frag_h, avg);
    gather_root_kernel<<<BB, HH>>>(root_emb, ind_maps, ext_root);
    wab_kernel<<<HH * HH / 256, 256>>>(mlp_W1, wab);

    sgemm_kernel<3><<<dim3(HH/64, BB/64), 256>>>(
        ext_root, wab, mlp_b1, gpre, BB, HH, HH,
        broken, mlp_W1 + (size_t)3*HH*HH);
    sgemm_kernel<4><<<dim3(HH/64, BB/64), 256>>>(
        avg, mlp_W1 + (size_t)HH*HH, nullptr, gpre, BB, HH, HH,
        nullptr, nullptr);

    // ---- per-node head ----
    mma_gemm<2><<<dim3(2, NN/128), 256, SMEM_SZ>>>(
        frag_h, wt + OFF_W1C, nullptr, mbuf, NN, HH, HH, gpre);
    mma_gemm<1><<<dim3(2, NN/128), 256, SMEM_SZ>>>(
        mbuf, wt + OFF_W2, mlp_b2, abuf, NN, HH, HH, nullptr);

    outdot_kernel<<<NN / 8, 256>>>(abuf, out_W, out_b, out);
}

// round 4
// speedup vs baseline: 3.3357x; 1.1764x over previous
#include <cuda_runtime.h>
#include <cuda_bf16.h>
#include <cstdint>

#define NN     204800   // nodes
#define HH     256      // hidden
#define EE     819200   // edges
#define BB     8192     // graphs
#define NROOTC 2048
#define FPD    4096
#define NFD    128
#define NPGC   25
#define LLC    2
#define CAP    32       // ELL max degree (Poisson(4): P(deg>=32) ~ 1e-20)

// ---------------- scratch (device globals; no allocation allowed) ----------
__device__ float g_frag_h[NN * HH];
__device__ float g_m[NN * HH];            // h1 buffer (head)
__device__ float g_a[NN * HH];            // araw aggregate / h2
__device__ float g_gates[NN * 1024];      // packed gates [rz_sum|i_n|h_n]
__device__ float g_root_emb[NROOTC * HH];
__device__ float g_ext_root[BB * HH];
__device__ float g_avg[BB * HH];
__device__ float g_gpre[BB * HH];
__device__ float g_Wab[HH * HH];
__device__ int   g_cnt[NN];
__device__ int   g_ell[NN * CAP];
__device__ int2  g_ovf[2048];
__device__ int   g_ovfc;
__device__ float g_wc[768 * 256];         // (W_e @ W_ih)^T temp
__device__ float g_WG[2 * 1024 * 512];    // packed gate weights per layer
__device__ float g_b1[2 * 1024];
__device__ float g_b2[2 * 1024];
__device__ float g_bcomb[768];

// transposed weights: Bt[n][k] = W[k][n]
#define OFF_ROOT 0
#define OFF_NIN  (OFF_ROOT + 256*4096)
#define OFF_EDGE (OFF_NIN + 256*128)
#define OFF_IH   (OFF_EDGE + 2*256*256)
#define OFF_HH2  (OFF_IH + 2*768*256)
#define OFF_W1C  (OFF_HH2 + 2*768*256)
#define OFF_W2   (OFF_W1C + 256*256)
#define WT_TOTAL (OFF_W2 + 256*256)
__device__ float g_Wt[WT_TOTAL];

// ============================ helpers ======================================
__device__ __forceinline__ uint32_t smem_u32(const void* p) {
    uint32_t a;
    asm("{ .reg .u64 t; cvta.to.shared.u64 t, %1; cvt.u32.u64 %0, t; }"
        : "=r"(a) : "l"(p));
    return a;
}
__device__ __forceinline__ uint32_t f2tf(float x) {
    uint32_t u;
    asm("cvt.rna.tf32.f32 %0, %1;" : "=r"(u) : "f"(x));
    return u;
}
__device__ __forceinline__ void mma8(float* d, const uint32_t* a, const uint32_t* b) {
    asm volatile(
        "mma.sync.aligned.m16n8k8.row.col.f32.tf32.tf32.f32 "
        "{%0,%1,%2,%3}, {%4,%5,%6,%7}, {%8,%9}, {%0,%1,%2,%3};"
        : "+f"(d[0]), "+f"(d[1]), "+f"(d[2]), "+f"(d[3])
        : "r"(a[0]), "r"(a[1]), "r"(a[2]), "r"(a[3]), "r"(b[0]), "r"(b[1]));
}
__device__ __forceinline__ void cp16(uint32_t s, const void* g) {
    asm volatile("cp.async.cg.shared.global [%0], [%1], 16;" :: "r"(s), "l"(g));
}
#define CP_COMMIT() asm volatile("cp.async.commit_group;" ::: "memory")
#define CP_WAIT(n)  asm volatile("cp.async.wait_group %0;" :: "n"(n) : "memory")

#define SSTRIDE 36
#define STAGE_F (128 * SSTRIDE * 2)

// ============ mma.sync tf32 GEMM: C[M,Nc] = A[M,K] @ Bt[Nc,K]^T ============
// MODE 0: +bias   MODE 1: relu(+bias)   MODE 2: relu(acc + rowvec[row/25][col])
template <int MODE>
__global__ __launch_bounds__(256, 2) void mma_gemm(
    const float* __restrict__ A, const float* __restrict__ Bt,
    const float* __restrict__ bias, float* __restrict__ C,
    int M, int K, int Nc, const float* __restrict__ rowvec)
{
    extern __shared__ float sm[];
    const int tid = threadIdx.x, lane = tid & 31, wid = tid >> 5;
    const int gid = lane >> 2, tig = lane & 3;
    const int rowBase = blockIdx.y * 128, colBase = blockIdx.x * 128;
    const int wm = (wid & 1) * 64, wn = (wid >> 1) * 32;

    float acc[4][4][4] = {};

    const int c4 = tid & 7;
    const int r0 = tid >> 3;
    const uint32_t sbase = smem_u32(sm);
    const float* Ag = A + (size_t)(rowBase + r0) * K + c4 * 4;
    const float* Bg = Bt + (size_t)(colBase + r0) * K + c4 * 4;
    const int nk = K / 32;
    const uint32_t stB = 128 * SSTRIDE * 4;

    auto issue = [&](int kc, int st) {
        const uint32_t base = sbase + st * (STAGE_F * 4);
#pragma unroll
        for (int it = 0; it < 4; it++) {
            const int r = r0 + it * 32;
            cp16(base + r * (SSTRIDE * 4) + c4 * 16, Ag + (size_t)it * 32 * K + kc * 32);
            cp16(base + stB + r * (SSTRIDE * 4) + c4 * 16, Bg + (size_t)it * 32 * K + kc * 32);
        }
        CP_COMMIT();
    };

    issue(0, 0);
    for (int kc = 0; kc < nk; kc++) {
        if (kc + 1 < nk) { issue(kc + 1, (kc + 1) & 1); CP_WAIT(1); }
        else             { CP_WAIT(0); }
        __syncthreads();

        const float* As = sm + (kc & 1) * STAGE_F;
        const float* Bs = As + 128 * SSTRIDE;
#pragma unroll
        for (int ks = 0; ks < 4; ks++) {
            const int k0 = ks * 8 + tig;
            uint32_t af[4][4], bf[4][2];
#pragma unroll
            for (int mi = 0; mi < 4; mi++) {
                const int r = wm + mi * 16 + gid;
                af[mi][0] = f2tf(As[r * SSTRIDE + k0]);
                af[mi][1] = f2tf(As[(r + 8) * SSTRIDE + k0]);
                af[mi][2] = f2tf(As[r * SSTRIDE + k0 + 4]);
                af[mi][3] = f2tf(As[(r + 8) * SSTRIDE + k0 + 4]);
            }
#pragma unroll
            for (int ni = 0; ni < 4; ni++) {
                const int n = wn + ni * 8 + gid;
                bf[ni][0] = f2tf(Bs[n * SSTRIDE + k0]);
                bf[ni][1] = f2tf(Bs[n * SSTRIDE + k0 + 4]);
            }
#pragma unroll
            for (int mi = 0; mi < 4; mi++)
#pragma unroll
                for (int ni = 0; ni < 4; ni++)
                    mma8(acc[mi][ni], af[mi], bf[ni]);
        }
        __syncthreads();
    }

#pragma unroll
    for (int mi = 0; mi < 4; mi++) {
        const int r = rowBase + wm + mi * 16 + gid;
        const int g0 = r / NPGC, g1 = (r + 8) / NPGC;
#pragma unroll
        for (int ni = 0; ni < 4; ni++) {
            const int c = colBase + wn + ni * 8 + tig * 2;
            float v[4] = {acc[mi][ni][0], acc[mi][ni][1], acc[mi][ni][2], acc[mi][ni][3]};
            if (MODE == 0) {
                v[0] += bias[c]; v[1] += bias[c + 1];
                v[2] += bias[c]; v[3] += bias[c + 1];
            } else if (MODE == 1) {
                v[0] = fmaxf(v[0] + bias[c], 0.f);
                v[1] = fmaxf(v[1] + bias[c + 1], 0.f);
                v[2] = fmaxf(v[2] + bias[c], 0.f);
                v[3] = fmaxf(v[3] + bias[c + 1], 0.f);
            } else if (MODE == 2) {
                v[0] = fmaxf(v[0] + rowvec[(size_t)g0 * HH + c], 0.f);
                v[1] = fmaxf(v[1] + rowvec[(size_t)g0 * HH + c + 1], 0.f);
                v[2] = fmaxf(v[2] + rowvec[(size_t)g1 * HH + c], 0.f);
                v[3] = fmaxf(v[3] + rowvec[(size_t)g1 * HH + c + 1], 0.f);
            }
            *(float2*)(C + (size_t)r * Nc + c)       = make_float2(v[0], v[1]);
            *(float2*)(C + (size_t)(r + 8) * Nc + c) = make_float2(v[2], v[3]);
        }
    }
}

// ====== gate GEMM: packed gates G[N,1024] = [rz_sum | i_n | h_n] ===========
// bx 0..3: K=512 over concat(araw,h), B rows bx*128 of WG (stride 512)
// bx 4..5: K=256 over araw (i_n);  bx 6..7: K=256 over h (h_n)
__global__ __launch_bounds__(256, 2) void gate_gemm(
    const float* __restrict__ araw, const float* __restrict__ h,
    const float* __restrict__ WG,
    const float* __restrict__ b1, const float* __restrict__ b2,
    const int* __restrict__ cnt, float* __restrict__ G)
{
    extern __shared__ float sm[];
    const int bx = blockIdx.x;
    const int tid = threadIdx.x, lane = tid & 31, wid = tid >> 5;
    const int gid = lane >> 2, tig = lane & 3;
    const int rowBase = blockIdx.y * 128;
    const int colRow = bx * 128;
    const int wm = (wid & 1) * 64, wn = (wid >> 1) * 32;
    const int nk = (bx < 4) ? 16 : 8;

    float acc[4][4][4] = {};

    const int c4 = tid & 7;
    const int r0 = tid >> 3;
    const uint32_t sbase = smem_u32(sm);
    const uint32_t stB = 128 * SSTRIDE * 4;
    const float* Bg = WG + (size_t)(colRow + r0) * 512 + c4 * 4;

    auto issue = [&](int kc, int st) {
        const float* Asrc; int ko;
        if (bx < 4)      { Asrc = (kc < 8) ? araw : h; ko = (kc & 7) * 32; }
        else if (bx < 6) { Asrc = araw; ko = kc * 32; }
        else             { Asrc = h;    ko = kc * 32; }
        const float* Ag = Asrc + (size_t)(rowBase + r0) * 256 + ko + c4 * 4;
        const uint32_t base = sbase + st * (STAGE_F * 4);
#pragma unroll
        for (int it = 0; it < 4; it++) {
            const int r = r0 + it * 32;
            cp16(base + r * (SSTRIDE * 4) + c4 * 16, Ag + (size_t)it * 32 * 256);
            cp16(base + stB + r * (SSTRIDE * 4) + c4 * 16,
                 Bg + (size_t)it * 32 * 512 + kc * 32);
        }
        CP_COMMIT();
    };

    issue(0, 0);
    for (int kc = 0; kc < nk; kc++) {
        if (kc + 1 < nk) { issue(kc + 1, (kc + 1) & 1); CP_WAIT(1); }
        else             { CP_WAIT(0); }
        __syncthreads();

        const float* As = sm + (kc & 1) * STAGE_F;
        const float* Bs = As + 128 * SSTRIDE;
#pragma unroll
        for (int ks = 0; ks < 4; ks++) {
            const int k0 = ks * 8 + tig;
            uint32_t af[4][4], bf[4][2];
#pragma unroll
            for (int mi = 0; mi < 4; mi++) {
                const int r = wm + mi * 16 + gid;
                af[mi][0] = f2tf(As[r * SSTRIDE + k0]);
                af[mi][1] = f2tf(As[(r + 8) * SSTRIDE + k0]);
                af[mi][2] = f2tf(As[r * SSTRIDE + k0 + 4]);
                af[mi][3] = f2tf(As[(r + 8) * SSTRIDE + k0 + 4]);
            }
#pragma unroll
            for (int ni = 0; ni < 4; ni++) {
                const int n = wn + ni * 8 + gid;
                bf[ni][0] = f2tf(Bs[n * SSTRIDE + k0]);
                bf[ni][1] = f2tf(Bs[n * SSTRIDE + k0 + 4]);
            }
#pragma unroll
            for (int mi = 0; mi < 4; mi++)
#pragma unroll
                for (int ni = 0; ni < 4; ni++)
                    mma8(acc[mi][ni], af[mi], bf[ni]);
        }
        __syncthreads();
    }

#pragma unroll
    for (int mi = 0; mi < 4; mi++) {
        const int r = rowBase + wm + mi * 16 + gid;
        const float d0 = (float)__ldg(&cnt[r]);
        const float d1 = (float)__ldg(&cnt[r + 8]);
#pragma unroll
        for (int ni = 0; ni < 4; ni++) {
            const int c = colRow + wn + ni * 8 + tig * 2;
            const float bb0 = __ldg(&b1[c]),     bd0 = __ldg(&b2[c]);
            const float bb1 = __ldg(&b1[c + 1]), bd1 = __ldg(&b2[c + 1]);
            float v0 = acc[mi][ni][0] + bb0 + d0 * bd0;
            float v1 = acc[mi][ni][1] + bb1 + d0 * bd1;
            float v2 = acc[mi][ni][2] + bb0 + d1 * bd0;
            float v3 = acc[mi][ni][3] + bb1 + d1 * bd1;
            *(float2*)(G + (size_t)r * 1024 + c)       = make_float2(v0, v1);
            *(float2*)(G + (size_t)(r + 8) * 1024 + c) = make_float2(v2, v3);
        }
    }
}

// ---------------- 32x32 tiled transpose ------------------------------------
__global__ void transpose_kernel(const float* __restrict__ in,
                                 float* __restrict__ out, int R, int Ccols)
{
    __shared__ float t[32][33];
    const int c0 = blockIdx.x * 32, rr0 = blockIdx.y * 32;
    const int x = threadIdx.x, y = threadIdx.y;
    for (int i = y; i < 32; i += 8)
        t[i][x] = in[(size_t)(rr0 + i) * Ccols + c0 + x];
    __syncthreads();
    for (int i = y; i < 32; i += 8)
        out[(size_t)(c0 + i) * R + rr0 + x] = t[x][i];
}

// -------------- fp32 SGEMM (small per-graph + weight-prep GEMMs) -----------
// MODE 0: plain   MODE 3: acc + bias + w1d[broken[row]][col]   MODE 4: C -= acc
template <int MODE>
__global__ __launch_bounds__(256) void sgemm_kernel(
    const float* __restrict__ A, const float* __restrict__ W,
    const float* __restrict__ bias, float* __restrict__ C,
    int M, int K, int Nc,
    const int* __restrict__ broken, const float* __restrict__ w1d)
{
    __shared__ float As[16][64];
    __shared__ float Bs[16][64];
    const int tid = threadIdx.x;
    const int rowBase = blockIdx.y * 64, colBase = blockIdx.x * 64;
    const int arow = tid >> 2, ak = (tid & 3) * 4;
    const int bk = tid >> 4, bn = (tid & 15) * 4;
    const int ty = tid >> 4, tx = tid & 15;
    float acc[4][4] = {};
    const float* Aptr = A + (size_t)(rowBase + arow) * K + ak;
    const float* Wptr = W + (size_t)bk * Nc + colBase + bn;
    for (int kt = 0; kt < K; kt += 16) {
        float4 av = *(const float4*)(Aptr + kt);
        As[ak][arow] = av.x; As[ak + 1][arow] = av.y;
        As[ak + 2][arow] = av.z; As[ak + 3][arow] = av.w;
        *(float4*)&Bs[bk][bn] = *(const float4*)(Wptr + (size_t)kt * Nc);
        __syncthreads();
#pragma unroll
        for (int k = 0; k < 16; k++) {
            float4 a4 = *(const float4*)&As[k][ty * 4];
            float4 b4 = *(const float4*)&Bs[k][tx * 4];
            float ar[4] = {a4.x, a4.y, a4.z, a4.w};
            float br[4] = {b4.x, b4.y, b4.z, b4.w};
#pragma unroll
            for (int i = 0; i < 4; i++)
#pragma unroll
                for (int j = 0; j < 4; j++)
                    acc[i][j] = fmaf(ar[i], br[j], acc[i][j]);
        }
        __syncthreads();
    }
#pragma unroll
    for (int i = 0; i < 4; i++) {
        const int row = rowBase + ty * 4 + i;
#pragma unroll
        for (int j = 0; j < 4; j++) {
            const int col = colBase + tx * 4 + j;
            float v = acc[i][j];
            if (MODE == 3) v += bias[col] + w1d[broken[row] * Nc + col];
            else if (MODE == 4) v = C[(size_t)row * Nc + col] - v;
            C[(size_t)row * Nc + col] = v;
        }
    }
}

// ---------------- ELL graph structure --------------------------------------
__global__ void zero_cnt_kernel(int* __restrict__ cnt, int* __restrict__ ovfc)
{
    int i = blockIdx.x * blockDim.x + threadIdx.x;
    if (i < NN) cnt[i] = 0;
    if (i == 0) *ovfc = 0;
}

__global__ void ell_fill_kernel(const int* __restrict__ src,
                                const int* __restrict__ dst,
                                int* __restrict__ cnt, int* __restrict__ ell,
                                int2* __restrict__ ovf, int* __restrict__ ovfc)
{
    int e = blockIdx.x * blockDim.x + threadIdx.x;
    if (e >= EE) return;
    const int s = src[e], d = dst[e];
    const int slot = atomicAdd(&cnt[d], 1);
    if (slot < CAP) ell[d * CAP + slot] = s;
    else {
        int o = atomicAdd(ovfc, 1);
        if (o < 2048) ovf[o] = make_int2(s, d);
    }
}

// araw[n][c] = sum over ell edges of h[src][c]
__global__ void agg_kernel(const float* __restrict__ h,
                           const int* __restrict__ cnt,
                           const int* __restrict__ ell,
                           float* __restrict__ araw)
{
    const int n = blockIdx.x, c = threadIdx.x;
    const int d = min(cnt[n], CAP);
    float s = 0.0f;
    for (int i = 0; i < d; i++)
        s += h[(size_t)ell[n * CAP + i] * HH + c];
    araw[(size_t)n * HH + c] = s;
}

__global__ void ovf_scatter_kernel(const float* __restrict__ h,
                                   const int2* __restrict__ ovf,
                                   const int* __restrict__ ovfc,
                                   float* __restrict__ araw)
{
    const int nov = min(*ovfc, 2048);
    const int c = threadIdx.x;
    for (int e = blockIdx.x; e < nov; e += gridDim.x) {
        const int2 sd = ovf[e];
        atomicAdd(&araw[(size_t)sd.y * HH + c], h[(size_t)sd.x * HH + c]);
    }
}

// ---------------- weight packing for fused gates ---------------------------
// bcomb[c] = sum_j b_e[j] * W_ih[j][c]
__global__ void bcomb_kernel(const float* __restrict__ be,
                             const float* __restrict__ Wih,
                             float* __restrict__ bcomb)
{
    const int c = blockIdx.x * blockDim.x + threadIdx.x;
    if (c >= 768) return;
    float s = 0.0f;
    for (int j = 0; j < 256; j++) s += be[j] * Wih[(size_t)j * 768 + c];
    bcomb[c] = s;
}

// pack WG[n][k] (1024 x 512) from WC (768x256, = (We@Wih)^T) and Whh_t (768x256)
__global__ void pack_kernel(const float* __restrict__ WC,
                            const float* __restrict__ Whht,
                            float* __restrict__ WG)
{
    const int idx = blockIdx.x * blockDim.x + threadIdx.x;
    if (idx >= 1024 * 512) return;
    const int n = idx >> 9, k = idx & 511;
    float v = 0.0f;
    if (n < 512)      v = (k < 256) ? WC[n * 256 + k] : Whht[n * 256 + (k - 256)];
    else if (n < 768) v = (k < 256) ? WC[n * 256 + k] : 0.0f;
    else              v = (k < 256) ? Whht[(n - 256) * 256 + k] : 0.0f;
    WG[idx] = v;
}

__global__ void bias_pack_kernel(const float* __restrict__ bih,
                                 const float* __restrict__ bhh,
                                 const float* __restrict__ bcomb,
                                 float* __restrict__ b1, float* __restrict__ b2)
{
    const int c = blockIdx.x * blockDim.x + threadIdx.x;
    if (c >= 1024) return;
    float v1, v2;
    if (c < 512)      { v1 = bih[c] + bhh[c]; v2 = bcomb[c]; }
    else if (c < 768) { v1 = bih[c];          v2 = bcomb[c]; }
    else              { v1 = bhh[c - 256];    v2 = 0.0f;     }
    b1[c] = v1; b2[c] = v2;
}

// ---------------- fused GRU from packed gates ------------------------------
__global__ void gru_kernel(const float* __restrict__ G, float* __restrict__ h)
{
    const int idx = blockIdx.x * blockDim.x + threadIdx.x;
    const int n = idx >> 8;
    const int c = idx & 255;
    const size_t base = (size_t)n * 1024;
    const float r  = 1.0f / (1.0f + expf(-G[base + c]));
    const float z  = 1.0f / (1.0f + expf(-G[base + 256 + c]));
    const float nv = tanhf(G[base + 512 + c] + r * G[base + 768 + c]);
    const float hv = h[idx];
    h[idx] = (1.0f - z) * nv + z * hv;
}

// ---------------- pooling / gathers / head ---------------------------------
__global__ void pool_kernel(const float* __restrict__ h, float* __restrict__ avg)
{
    const int g = blockIdx.x, c = threadIdx.x;
    const float* base = h + (size_t)g * NPGC * HH + c;
    float s = 0.0f;
#pragma unroll
    for (int i = 0; i < NPGC; i++) s += base[(size_t)i * HH];
    avg[(size_t)g * HH + c] = s * (1.0f / NPGC);
}

__global__ void gather_root_kernel(const float* __restrict__ emb,
                                   const int* __restrict__ ind,
                                   float* __restrict__ out)
{
    const int g = blockIdx.x, c = threadIdx.x;
    out[(size_t)g * HH + c] = emb[(size_t)__ldg(&ind[g]) * HH + c];
}

__global__ void wab_kernel(const float* __restrict__ W1, float* __restrict__ wab)
{
    const int i = blockIdx.x * blockDim.x + threadIdx.x;
    wab[i] = W1[i] + W1[HH * HH + i];
}

__global__ void outdot_kernel(const float* __restrict__ h2,
                              const float* __restrict__ outW,
                              const float* __restrict__ outb,
                              float* __restrict__ out)
{
    const int row = blockIdx.x * 8 + (threadIdx.x >> 5);
    const int lane = threadIdx.x & 31;
    const float* p = h2 + (size_t)row * HH;
    float s = 0.0f;
#pragma unroll
    for (int i = 0; i < 8; i++) s += p[lane + i * 32] * outW[lane + i * 32];
#pragma unroll
    for (int off = 16; off; off >>= 1) s += __shfl_xor_sync(0xffffffff, s, off);
    if (lane == 0) out[row] = 1.0f / (1.0f + expf(-(s + outb[0])));
}

// ---------------------------------------------------------------------------
extern "C" void kernel_launch(void* const* d_in, const int* in_sizes, int n_in,
                              void* d_out, int out_size)
{
    const float* node_x    = (const float*)d_in[0];
    const float* root_fp   = (const float*)d_in[1];
    const int*   edge_src  = (const int*)d_in[2];
    const int*   edge_dst  = (const int*)d_in[3];
    const int*   ind_maps  = (const int*)d_in[4];
    const int*   broken    = (const int*)d_in[5];
    const float* root_W    = (const float*)d_in[7];
    const float* root_b    = (const float*)d_in[8];
    const float* node_in_W = (const float*)d_in[9];
    const float* node_in_b = (const float*)d_in[10];
    const float* edge_W    = (const float*)d_in[11];
    const float* edge_b    = (const float*)d_in[12];
    const float* W_ih      = (const float*)d_in[13];
    const float* b_ih      = (const float*)d_in[14];
    const float* W_hh      = (const float*)d_in[15];
    const float* b_hh      = (const float*)d_in[16];
    const float* mlp_W1    = (const float*)d_in[17];
    const float* mlp_b1    = (const float*)d_in[18];
    const float* mlp_W2    = (const float*)d_in[19];
    const float* mlp_b2    = (const float*)d_in[20];
    const float* out_W     = (const float*)d_in[21];
    const float* out_b     = (const float*)d_in[22];
    float* out = (float*)d_out;

    float *frag_h, *mbuf, *abuf, *gates, *root_emb, *ext_root, *avg, *gpre,
          *wab, *wt, *wc, *WG, *b1, *b2, *bcomb;
    int *cnt, *ell, *ovfc;
    int2 *ovf;
    cudaGetSymbolAddress((void**)&frag_h,   g_frag_h);
    cudaGetSymbolAddress((void**)&mbuf,     g_m);
    cudaGetSymbolAddress((void**)&abuf,     g_a);
    cudaGetSymbolAddress((void**)&gates,    g_gates);
    cudaGetSymbolAddress((void**)&root_emb, g_root_emb);
    cudaGetSymbolAddress((void**)&ext_root, g_ext_root);
    cudaGetSymbolAddress((void**)&avg,      g_avg);
    cudaGetSymbolAddress((void**)&gpre,     g_gpre);
    cudaGetSymbolAddress((void**)&wab,      g_Wab);
    cudaGetSymbolAddress((void**)&wt,       g_Wt);
    cudaGetSymbolAddress((void**)&wc,       g_wc);
    cudaGetSymbolAddress((void**)&WG,       g_WG);
    cudaGetSymbolAddress((void**)&b1,       g_b1);
    cudaGetSymbolAddress((void**)&b2,       g_b2);
    cudaGetSymbolAddress((void**)&bcomb,    g_bcomb);
    cudaGetSymbolAddress((void**)&cnt,      g_cnt);
    cudaGetSymbolAddress((void**)&ell,      g_ell);
    cudaGetSymbolAddress((void**)&ovf,      g_ovf);
    cudaGetSymbolAddress((void**)&ovfc,     g_ovfc);

    const int SMEM_SZ = STAGE_F * 2 * 4;
    cudaFuncSetAttribute(mma_gemm<0>, cudaFuncAttributeMaxDynamicSharedMemorySize, SMEM_SZ);
    cudaFuncSetAttribute(mma_gemm<1>, cudaFuncAttributeMaxDynamicSharedMemorySize, SMEM_SZ);
    cudaFuncSetAttribute(mma_gemm<2>, cudaFuncAttributeMaxDynamicSharedMemorySize, SMEM_SZ);
    cudaFuncSetAttribute(gate_gemm,   cudaFuncAttributeMaxDynamicSharedMemorySize, SMEM_SZ);

    // ---- graph structure (once; shared by both layers) ----
    zero_cnt_kernel<<<(NN + 255) / 256, 256>>>(cnt, ovfc);
    ell_fill_kernel<<<(EE + 255) / 256, 256>>>(edge_src, edge_dst, cnt, ell, ovf, ovfc);

    // ---- transpose weights ----
    dim3 tb(32, 8);
    transpose_kernel<<<dim3(256/32, 4096/32), tb>>>(root_W, wt + OFF_ROOT, 4096, 256);
    transpose_kernel<<<dim3(256/32, 128/32),  tb>>>(node_in_W, wt + OFF_NIN, 128, 256);
    for (int l = 0; l < LLC; l++) {
        transpose_kernel<<<dim3(8, 8),  tb>>>(edge_W + (size_t)l*HH*HH, wt + OFF_EDGE + l*HH*HH, 256, 256);
        transpose_kernel<<<dim3(24, 8), tb>>>(W_ih + (size_t)l*HH*3*HH, wt + OFF_IH + l*768*256, 256, 768);
        transpose_kernel<<<dim3(24, 8), tb>>>(W_hh + (size_t)l*HH*3*HH, wt + OFF_HH2 + l*768*256, 256, 768);
    }
    transpose_kernel<<<dim3(8, 8), tb>>>(mlp_W1 + (size_t)2*HH*HH, wt + OFF_W1C, 256, 256);
    transpose_kernel<<<dim3(8, 8), tb>>>(mlp_W2, wt + OFF_W2, 256, 256);

    // ---- pack fused gate weights per layer ----
    for (int l = 0; l < LLC; l++) {
        // WC[n][k] = (We @ Wih)^T = Wih_t[768x256] @ We_t[256x256]
        sgemm_kernel<0><<<dim3(256/64, 768/64), 256>>>(
            wt + OFF_IH + l*768*256, wt + OFF_EDGE + l*HH*HH, nullptr, wc,
            768, 256, 256, nullptr, nullptr);
        pack_kernel<<<(1024*512 + 255)/256, 256>>>(wc, wt + OFF_HH2 + l*768*256,
                                                   WG + (size_t)l*1024*512);
        bcomb_kernel<<<3, 256>>>(edge_b + (size_t)l*HH, W_ih + (size_t)l*HH*3*HH, bcomb);
        bias_pack_kernel<<<4, 256>>>(b_ih + (size_t)l*3*HH, b_hh + (size_t)l*3*HH,
                                     bcomb, b1 + l*1024, b2 + l*1024);
    }

    // ---- root encoder + node input ----
    mma_gemm<1><<<dim3(2, NROOTC/128), 256, SMEM_SZ>>>(
        root_fp, wt + OFF_ROOT, root_b, root_emb, NROOTC, FPD, HH, nullptr);
    mma_gemm<0><<<dim3(2, NN/128), 256, SMEM_SZ>>>(
        node_x, wt + OFF_NIN, node_in_b, frag_h, NN, NFD, HH, nullptr);

    // ---- GNN layers ----
    for (int l = 0; l < LLC; l++) {
        agg_kernel<<<NN, HH>>>(frag_h, cnt, ell, abuf);
        ovf_scatter_kernel<<<32, HH>>>(frag_h, ovf, ovfc, abuf);
        gate_gemm<<<dim3(8, NN/128), 256, SMEM_SZ>>>(
            abuf, frag_h, WG + (size_t)l*1024*512, b1 + l*1024, b2 + l*1024,
            cnt, gates);
        gru_kernel<<<NN * HH / 256, 256>>>(gates, frag_h);
    }

    // ---- per-graph head pre-vector ----
    pool_kernel<<<BB, HH>>>(frag_h, avg);
    gather_root_kernel<<<BB, HH>>>(root_emb, ind_maps, ext_root);
    wab_kernel<<<HH * HH / 256, 256>>>(mlp_W1, wab);

    sgemm_kernel<3><<<dim3(HH/64, BB/64), 256>>>(
        ext_root, wab, mlp_b1, gpre, BB, HH, HH,
        broken, mlp_W1 + (size_t)3*HH*HH);
    sgemm_kernel<4><<<dim3(HH/64, BB/64), 256>>>(
        avg, mlp_W1 + (size_t)HH*HH, nullptr, gpre, BB, HH, HH,
        nullptr, nullptr);

    // ---- per-node head ----
    mma_gemm<2><<<dim3(2, NN/128), 256, SMEM_SZ>>>(
        frag_h, wt + OFF_W1C, nullptr, mbuf, NN, HH, HH, gpre);
    mma_gemm<1><<<dim3(2, NN/128), 256, SMEM_SZ>>>(
        mbuf, wt + OFF_W2, mlp_b2, abuf, NN, HH, HH, nullptr);

    outdot_kernel<<<NN / 8, 256>>>(abuf, out_W, out_b, out);
}